// round 1
// baseline (speedup 1.0000x reference)
#include <cuda_runtime.h>
#include <math.h>

#define NN 224
#define HW (NN*NN)
#define BATCH 32

// d_out offsets (floats), in reference return order:
// h1n, c1n, h2n, c2n, h3n, c3n, reconstruction, fovea, hr, hidden
#define SZ8  ((size_t)BATCH*8*HW)    // 12,845,056
#define SZ16 ((size_t)BATCH*16*HW)   // 25,690,112
#define SZ3  ((size_t)BATCH*3*HW)    //  4,816,896
#define OFF_H1     ((size_t)0)
#define OFF_C1     (OFF_H1 + SZ8)
#define OFF_H2     (OFF_C1 + SZ8)
#define OFF_C2     (OFF_H2 + SZ16)
#define OFF_H3     (OFF_C2 + SZ16)
#define OFF_C3     (OFF_H3 + SZ3)
#define OFF_RECON  (OFF_C3 + SZ3)
#define OFF_FOVEA  (OFF_RECON + SZ3)
#define OFF_HR     (OFF_FOVEA + SZ3)
#define OFF_HIDDEN (OFF_HR + SZ3)

__device__ __forceinline__ float sigf(float x) {
    return 1.0f / (1.0f + expf(-x));
}

// ---------------------------------------------------------------------------
// Kernel 1: mask + fovea (= r_t0) + hr
// ---------------------------------------------------------------------------
__global__ void mask_kernel(const float* __restrict__ x,
                            const float* __restrict__ rand_mask,
                            const int*   __restrict__ samples,
                            float* __restrict__ fovea,
                            float* __restrict__ hr)
{
    int idx = blockIdx.x * blockDim.x + threadIdx.x;   // over BATCH*HW
    if (idx >= BATCH * HW) return;
    int b = idx / HW;
    int p = idx - b * HW;
    int y  = p / NN;
    int xx = p - y * NN;
    int s  = samples[b];
    int px = s / 7;
    int py = s - px * 7;
    bool patch = (y  >= px*32) && (y  < px*32 + 32) &&
                 (xx >= py*32) && (xx < py*32 + 32);
    bool m = (rand_mask[idx] > 0.95f) || patch;
    float fm = m     ? 1.0f : 0.0f;
    float fp = patch ? 1.0f : 0.0f;
#pragma unroll
    for (int c = 0; c < 3; c++) {
        float v = x[((size_t)b*3 + c)*HW + p];
        fovea[((size_t)b*3 + c)*HW + p] = v * fm;
        hr   [((size_t)b*3 + c)*HW + p] = v * fp;
    }
}

// ---------------------------------------------------------------------------
// Kernel 2: fused ConvLSTM step. CX = x-input channels, CH = hidden channels.
// conv over concat([x, h]) producing 4*CH gate channels (i, f, o, g order),
// then gating + activations, writes h_next / c_next.
// 32x32 output tile per block, 256 threads (32x8), 4 pixels (rows) per thread.
// Dynamic smem: CIN channel tiles of 34x34 halo + full weight tensor.
// ---------------------------------------------------------------------------
template<int CX, int CH>
__global__ void __launch_bounds__(256, 1)
convlstm_kernel(const float* __restrict__ xin,
                const float* __restrict__ hin,
                const float* __restrict__ cin,
                const float* __restrict__ w,
                const float* __restrict__ bias,
                float* __restrict__ hout,
                float* __restrict__ cout)
{
    constexpr int CIN  = CX + CH;
    constexpr int TSZ  = 34 * 34;           // halo tile per channel
    constexpr int WSZ  = 4 * CH * CIN * 9;

    extern __shared__ float smem[];
    float* s_in = smem;                     // CIN * TSZ
    float* s_w  = smem + CIN * TSZ;         // WSZ

    const int tx  = threadIdx.x;            // 0..31
    const int ty  = threadIdx.y;            // 0..7
    const int tid = ty * 32 + tx;
    const int x0  = blockIdx.x * 32;
    const int y0  = blockIdx.y * 32;
    const int b   = blockIdx.z;

    // --- load input halo tiles ---
    for (int ci = 0; ci < CIN; ci++) {
        const float* src = (ci < CX)
            ? xin + ((size_t)b*CX + ci)      * HW
            : hin + ((size_t)b*CH + (ci-CX)) * HW;
        float* dst = s_in + ci * TSZ;
        for (int i = tid; i < TSZ; i += 256) {
            int yy = i / 34;
            int xx = i - yy * 34;
            int gy = y0 + yy - 1;
            int gx = x0 + xx - 1;
            float v = 0.0f;
            if (gy >= 0 && gy < NN && gx >= 0 && gx < NN)
                v = src[gy * NN + gx];
            dst[i] = v;
        }
    }
    // --- load weights ---
    for (int i = tid; i < WSZ; i += 256) s_w[i] = w[i];
    __syncthreads();

    for (int ch = 0; ch < CH; ch++) {
        float acc0[4], acc1[4], acc2[4], acc3[4];
        const float b0 = bias[0*CH + ch];
        const float b1 = bias[1*CH + ch];
        const float b2 = bias[2*CH + ch];
        const float b3 = bias[3*CH + ch];
#pragma unroll
        for (int p = 0; p < 4; p++) {
            acc0[p] = b0; acc1[p] = b1; acc2[p] = b2; acc3[p] = b3;
        }
        const float* w0 = s_w + (0*CH + ch) * CIN * 9;
        const float* w1 = s_w + (1*CH + ch) * CIN * 9;
        const float* w2 = s_w + (2*CH + ch) * CIN * 9;
        const float* w3 = s_w + (3*CH + ch) * CIN * 9;

        for (int ci = 0; ci < CIN; ci++) {
            const float* tile = s_in + ci * TSZ;
            const int wb = ci * 9;
#pragma unroll
            for (int dy = 0; dy < 3; dy++) {
#pragma unroll
                for (int dx = 0; dx < 3; dx++) {
                    const int k  = wb + dy*3 + dx;
                    const float wi = w0[k];
                    const float wf = w1[k];
                    const float wo = w2[k];
                    const float wg = w3[k];
#pragma unroll
                    for (int p = 0; p < 4; p++) {
                        float v = tile[(ty + p*8 + dy)*34 + tx + dx];
                        acc0[p] += v * wi;
                        acc1[p] += v * wf;
                        acc2[p] += v * wo;
                        acc3[p] += v * wg;
                    }
                }
            }
        }
#pragma unroll
        for (int p = 0; p < 4; p++) {
            int y = y0 + ty + p*8;
            size_t gidx = ((size_t)b*CH + ch)*HW + (size_t)y*NN + x0 + tx;
            float ig = sigf(acc0[p]);
            float fg = sigf(acc1[p]);
            float og = sigf(acc2[p]);
            float gg = tanhf(acc3[p]);
            float cp = cin[gidx];
            float cn = fg * cp + ig * gg;
            float hn = og * tanhf(cn);
            cout[gidx] = cn;
            hout[gidx] = hn;
        }
    }
}

// ---------------------------------------------------------------------------
// Kernel 3: reconstruction conv (3ch -> 3ch, 3x3) + hidden = h3n copy
// ---------------------------------------------------------------------------
__global__ void __launch_bounds__(256, 4)
recon_kernel(const float* __restrict__ h3,
             const float* __restrict__ wc,
             const float* __restrict__ bc,
             float* __restrict__ recon,
             float* __restrict__ hidden)
{
    __shared__ float s_in[3 * 34 * 34];
    __shared__ float s_w[3 * 3 * 9];
    __shared__ float s_b[3];

    const int tx  = threadIdx.x;
    const int ty  = threadIdx.y;
    const int tid = ty * 32 + tx;
    const int x0  = blockIdx.x * 32;
    const int y0  = blockIdx.y * 32;
    const int b   = blockIdx.z;

    for (int ci = 0; ci < 3; ci++) {
        const float* src = h3 + ((size_t)b*3 + ci) * HW;
        float* dst = s_in + ci * 1156;
        for (int i = tid; i < 1156; i += 256) {
            int yy = i / 34;
            int xx = i - yy * 34;
            int gy = y0 + yy - 1;
            int gx = x0 + xx - 1;
            float v = 0.0f;
            if (gy >= 0 && gy < NN && gx >= 0 && gx < NN)
                v = src[gy * NN + gx];
            dst[i] = v;
        }
    }
    if (tid < 81) s_w[tid] = wc[tid];
    if (tid < 3)  s_b[tid] = bc[tid];
    __syncthreads();

    for (int co = 0; co < 3; co++) {
        float acc[4];
#pragma unroll
        for (int p = 0; p < 4; p++) acc[p] = s_b[co];
        for (int ci = 0; ci < 3; ci++) {
            const float* tile = s_in + ci * 1156;
            const float* wp   = s_w + (co*3 + ci) * 9;
#pragma unroll
            for (int dy = 0; dy < 3; dy++) {
#pragma unroll
                for (int dx = 0; dx < 3; dx++) {
                    float wv = wp[dy*3 + dx];
#pragma unroll
                    for (int p = 0; p < 4; p++) {
                        float v = tile[(ty + p*8 + dy)*34 + tx + dx];
                        acc[p] += v * wv;
                    }
                }
            }
        }
#pragma unroll
        for (int p = 0; p < 4; p++) {
            int y = y0 + ty + p*8;
            size_t gidx = ((size_t)b*3 + co)*HW + (size_t)y*NN + x0 + tx;
            recon[gidx]  = acc[p];
            // hidden = h3n copy (center of halo tile for this channel/pixel)
            hidden[gidx] = s_in[co*1156 + (ty + p*8 + 1)*34 + tx + 1];
        }
    }
}

// ---------------------------------------------------------------------------
extern "C" void kernel_launch(void* const* d_in, const int* in_sizes, int n_in,
                              void* d_out, int out_size)
{
    const float* x         = (const float*)d_in[0];
    // d_in[1] = target (unused)
    const float* h1        = (const float*)d_in[2];
    const float* c1        = (const float*)d_in[3];
    const float* h2        = (const float*)d_in[4];
    const float* c2        = (const float*)d_in[5];
    const float* h3        = (const float*)d_in[6];
    const float* c3        = (const float*)d_in[7];
    const float* rand_mask = (const float*)d_in[8];
    const int*   samples   = (const int*)  d_in[9];
    const float* w1        = (const float*)d_in[10];
    const float* b1        = (const float*)d_in[11];
    const float* w2        = (const float*)d_in[12];
    const float* b2        = (const float*)d_in[13];
    const float* w3        = (const float*)d_in[14];
    const float* b3        = (const float*)d_in[15];
    const float* wc        = (const float*)d_in[16];
    const float* bc        = (const float*)d_in[17];
    float* out = (float*)d_out;

    // dynamic smem sizes
    const int smem1 = (11*34*34 + 4*8*11*9)  * 4;   //  63,536 B
    const int smem2 = (24*34*34 + 4*16*24*9) * 4;   // 166,272 B
    const int smem3 = (19*34*34 + 4*3*19*9)  * 4;   //  96,064 B
    cudaFuncSetAttribute(convlstm_kernel<3,8>,
        cudaFuncAttributeMaxDynamicSharedMemorySize, smem1);
    cudaFuncSetAttribute(convlstm_kernel<8,16>,
        cudaFuncAttributeMaxDynamicSharedMemorySize, smem2);
    cudaFuncSetAttribute(convlstm_kernel<16,3>,
        cudaFuncAttributeMaxDynamicSharedMemorySize, smem3);

    // 1) mask -> fovea (r_t0), hr
    {
        int total = BATCH * HW;
        mask_kernel<<<(total + 255)/256, 256>>>(
            x, rand_mask, samples, out + OFF_FOVEA, out + OFF_HR);
    }

    dim3 grid(NN/32, NN/32, BATCH);   // (7, 7, 32)
    dim3 blk(32, 8);

    // 2) ConvLSTM 1: in = r_t0(3) + h1(8) -> h1n, c1n
    convlstm_kernel<3,8><<<grid, blk, smem1>>>(
        out + OFF_FOVEA, h1, c1, w1, b1, out + OFF_H1, out + OFF_C1);

    // 3) ConvLSTM 2: in = h1n(8) + h2(16) -> h2n, c2n
    convlstm_kernel<8,16><<<grid, blk, smem2>>>(
        out + OFF_H1, h2, c2, w2, b2, out + OFF_H2, out + OFF_C2);

    // 4) ConvLSTM 3: in = h2n(16) + h3(3) -> h3n, c3n
    convlstm_kernel<16,3><<<grid, blk, smem3>>>(
        out + OFF_H2, h3, c3, w3, b3, out + OFF_H3, out + OFF_C3);

    // 5) reconstruction + hidden copy
    recon_kernel<<<grid, blk>>>(
        out + OFF_H3, wc, bc, out + OFF_RECON, out + OFF_HIDDEN);
}

// round 2
// speedup vs baseline: 1.2382x; 1.2382x over previous
#include <cuda_runtime.h>
#include <math.h>

#define NN 224
#define HW (NN*NN)
#define BATCH 32

typedef unsigned long long ull;

// d_out offsets (floats), in reference return order:
// h1n, c1n, h2n, c2n, h3n, c3n, reconstruction, fovea, hr, hidden
#define SZ8  ((size_t)BATCH*8*HW)
#define SZ16 ((size_t)BATCH*16*HW)
#define SZ3  ((size_t)BATCH*3*HW)
#define OFF_H1     ((size_t)0)
#define OFF_C1     (OFF_H1 + SZ8)
#define OFF_H2     (OFF_C1 + SZ8)
#define OFF_C2     (OFF_H2 + SZ16)
#define OFF_H3     (OFF_C2 + SZ16)
#define OFF_C3     (OFF_H3 + SZ3)
#define OFF_RECON  (OFF_C3 + SZ3)
#define OFF_FOVEA  (OFF_RECON + SZ3)
#define OFF_HR     (OFF_FOVEA + SZ3)
#define OFF_HIDDEN (OFF_HR + SZ3)

__device__ __forceinline__ float sigf(float x) {
    return 1.0f / (1.0f + expf(-x));
}

// ---- packed f32x2 helpers (sm_103a) --------------------------------------
__device__ __forceinline__ ull pack2(float lo, float hi) {
    ull r;
    asm("mov.b64 %0, {%1, %2};" : "=l"(r) : "f"(lo), "f"(hi));
    return r;
}
__device__ __forceinline__ void unpack2(ull v, float& lo, float& hi) {
    asm("mov.b64 {%0, %1}, %2;" : "=f"(lo), "=f"(hi) : "l"(v));
}
__device__ __forceinline__ ull fma2(ull a, ull b, ull c) {
    ull d;
    asm("fma.rn.f32x2 %0, %1, %2, %3;" : "=l"(d) : "l"(a), "l"(b), "l"(c));
    return d;
}

// ---------------------------------------------------------------------------
// Kernel 1: mask + fovea (= r_t0) + hr
// ---------------------------------------------------------------------------
__global__ void mask_kernel(const float* __restrict__ x,
                            const float* __restrict__ rand_mask,
                            const int*   __restrict__ samples,
                            float* __restrict__ fovea,
                            float* __restrict__ hr)
{
    int idx = blockIdx.x * blockDim.x + threadIdx.x;
    if (idx >= BATCH * HW) return;
    int b = idx / HW;
    int p = idx - b * HW;
    int y  = p / NN;
    int xx = p - y * NN;
    int s  = samples[b];
    int px = s / 7;
    int py = s - px * 7;
    bool patch = (y  >= px*32) && (y  < px*32 + 32) &&
                 (xx >= py*32) && (xx < py*32 + 32);
    bool m = (rand_mask[idx] > 0.95f) || patch;
    float fm = m     ? 1.0f : 0.0f;
    float fp = patch ? 1.0f : 0.0f;
#pragma unroll
    for (int c = 0; c < 3; c++) {
        float v = x[((size_t)b*3 + c)*HW + p];
        fovea[((size_t)b*3 + c)*HW + p] = v * fm;
        hr   [((size_t)b*3 + c)*HW + p] = v * fp;
    }
}

// ---------------------------------------------------------------------------
// Kernel 2: fused ConvLSTM step, f32x2 packed gate-pairs.
// 32x32 tile, 256 flat threads: thread (tx, tyy) handles col tx,
// 4 CONSECUTIVE rows tyy*4 .. tyy*4+3.
// smem: CIN halo tiles (34x34) + weights reordered [ch][ci][tap][gate]
// so LDS.64 gives packed (w_i,w_f) / (w_o,w_g).
// ---------------------------------------------------------------------------
template<int CX, int CH, int CHB>
__global__ void __launch_bounds__(256, 1)
convlstm2(const float* __restrict__ xin,
          const float* __restrict__ hin,
          const float* __restrict__ cin,
          const float* __restrict__ w,
          const float* __restrict__ bias,
          float* __restrict__ hout,
          float* __restrict__ cout)
{
    constexpr int CIN = CX + CH;
    constexpr int TSZ = 34 * 34;
    constexpr int WSZ = 4 * CH * CIN * 9;

    extern __shared__ float smem[];
    float* s_in = smem;                 // CIN * TSZ
    float* s_w  = smem + CIN * TSZ;     // WSZ, reordered

    const int tid = threadIdx.x;
    const int tx  = tid & 31;
    const int tyy = tid >> 5;
    const int x0  = blockIdx.x * 32;
    const int y0  = blockIdx.y * 32;
    const int b   = blockIdx.z;

    // input halo tiles
    for (int ci = 0; ci < CIN; ci++) {
        const float* src = (ci < CX)
            ? xin + ((size_t)b*CX + ci)      * HW
            : hin + ((size_t)b*CH + (ci-CX)) * HW;
        float* dst = s_in + ci * TSZ;
        for (int i = tid; i < TSZ; i += 256) {
            int yy = i / 34;
            int xx = i - yy * 34;
            int gy = y0 + yy - 1;
            int gx = x0 + xx - 1;
            float v = 0.0f;
            if (gy >= 0 && gy < NN && gx >= 0 && gx < NN)
                v = src[gy * NN + gx];
            dst[i] = v;
        }
    }
    // weights: global [gate*CH+ch][ci][tap] -> smem [ch][ci][tap][gate]
    for (int s = tid; s < WSZ; s += 256) {
        int g    = s & 3;
        int t    = (s >> 2) % 9;
        int rest = (s >> 2) / 9;        // ch*CIN + ci
        int ci   = rest % CIN;
        int ch   = rest / CIN;
        s_w[s] = w[((g*CH + ch)*CIN + ci)*9 + t];
    }
    __syncthreads();

    const int r0 = tyy * 4;             // top output row within tile

    for (int chb = 0; chb < CH; chb += CHB) {
        ull acc_if[CHB][4], acc_og[CHB][4];
#pragma unroll
        for (int c = 0; c < CHB; c++) {
            int ch = chb + c;
            ull bif = pack2(bias[ch],        bias[CH + ch]);
            ull bog = pack2(bias[2*CH + ch], bias[3*CH + ch]);
#pragma unroll
            for (int p = 0; p < 4; p++) { acc_if[c][p] = bif; acc_og[c][p] = bog; }
        }

        for (int ci = 0; ci < CIN; ci++) {
            const float* tile = s_in + ci * TSZ + r0 * 34 + tx;
            ull vd[6][3];
#pragma unroll
            for (int k = 0; k < 6; k++)
#pragma unroll
                for (int dx = 0; dx < 3; dx++) {
                    float v = tile[k*34 + dx];
                    vd[k][dx] = pack2(v, v);
                }
#pragma unroll
            for (int c = 0; c < CHB; c++) {
                const ull* wp = (const ull*)(s_w + ((chb + c)*CIN + ci) * 36);
#pragma unroll
                for (int dy = 0; dy < 3; dy++)
#pragma unroll
                    for (int dx = 0; dx < 3; dx++) {
                        ull wif = wp[(dy*3 + dx)*2];
                        ull wog = wp[(dy*3 + dx)*2 + 1];
#pragma unroll
                        for (int p = 0; p < 4; p++) {
                            acc_if[c][p] = fma2(vd[p + dy][dx], wif, acc_if[c][p]);
                            acc_og[c][p] = fma2(vd[p + dy][dx], wog, acc_og[c][p]);
                        }
                    }
            }
        }

        // epilogue: gating + activations
#pragma unroll
        for (int c = 0; c < CHB; c++) {
            int ch = chb + c;
#pragma unroll
            for (int p = 0; p < 4; p++) {
                float zi, zf, zo, zg;
                unpack2(acc_if[c][p], zi, zf);
                unpack2(acc_og[c][p], zo, zg);
                int y = y0 + r0 + p;
                size_t gidx = ((size_t)b*CH + ch)*HW + (size_t)y*NN + x0 + tx;
                float ig = sigf(zi);
                float fg = sigf(zf);
                float og = sigf(zo);
                float gg = tanhf(zg);
                float cp = cin[gidx];
                float cn = fg * cp + ig * gg;
                cout[gidx] = cn;
                hout[gidx] = og * tanhf(cn);
            }
        }
    }
}

// ---------------------------------------------------------------------------
// Kernel 3: reconstruction conv (3->3, 3x3) + hidden = h3n copy
// ---------------------------------------------------------------------------
__global__ void __launch_bounds__(256, 4)
recon_kernel(const float* __restrict__ h3,
             const float* __restrict__ wc,
             const float* __restrict__ bc,
             float* __restrict__ recon,
             float* __restrict__ hidden)
{
    __shared__ float s_in[3 * 34 * 34];
    __shared__ float s_w[3 * 3 * 9];
    __shared__ float s_b[3];

    const int tx  = threadIdx.x;
    const int ty  = threadIdx.y;
    const int tid = ty * 32 + tx;
    const int x0  = blockIdx.x * 32;
    const int y0  = blockIdx.y * 32;
    const int b   = blockIdx.z;

    for (int ci = 0; ci < 3; ci++) {
        const float* src = h3 + ((size_t)b*3 + ci) * HW;
        float* dst = s_in + ci * 1156;
        for (int i = tid; i < 1156; i += 256) {
            int yy = i / 34;
            int xx = i - yy * 34;
            int gy = y0 + yy - 1;
            int gx = x0 + xx - 1;
            float v = 0.0f;
            if (gy >= 0 && gy < NN && gx >= 0 && gx < NN)
                v = src[gy * NN + gx];
            dst[i] = v;
        }
    }
    if (tid < 81) s_w[tid] = wc[tid];
    if (tid < 3)  s_b[tid] = bc[tid];
    __syncthreads();

    for (int co = 0; co < 3; co++) {
        float acc[4];
#pragma unroll
        for (int p = 0; p < 4; p++) acc[p] = s_b[co];
        for (int ci = 0; ci < 3; ci++) {
            const float* tile = s_in + ci * 1156;
            const float* wp   = s_w + (co*3 + ci) * 9;
#pragma unroll
            for (int dy = 0; dy < 3; dy++)
#pragma unroll
                for (int dx = 0; dx < 3; dx++) {
                    float wv = wp[dy*3 + dx];
#pragma unroll
                    for (int p = 0; p < 4; p++) {
                        float v = tile[(ty + p*8 + dy)*34 + tx + dx];
                        acc[p] += v * wv;
                    }
                }
        }
#pragma unroll
        for (int p = 0; p < 4; p++) {
            int y = y0 + ty + p*8;
            size_t gidx = ((size_t)b*3 + co)*HW + (size_t)y*NN + x0 + tx;
            recon[gidx]  = acc[p];
            hidden[gidx] = s_in[co*1156 + (ty + p*8 + 1)*34 + tx + 1];
        }
    }
}

// ---------------------------------------------------------------------------
extern "C" void kernel_launch(void* const* d_in, const int* in_sizes, int n_in,
                              void* d_out, int out_size)
{
    const float* x         = (const float*)d_in[0];
    const float* h1        = (const float*)d_in[2];
    const float* c1        = (const float*)d_in[3];
    const float* h2        = (const float*)d_in[4];
    const float* c2        = (const float*)d_in[5];
    const float* h3        = (const float*)d_in[6];
    const float* c3        = (const float*)d_in[7];
    const float* rand_mask = (const float*)d_in[8];
    const int*   samples   = (const int*)  d_in[9];
    const float* w1        = (const float*)d_in[10];
    const float* b1        = (const float*)d_in[11];
    const float* w2        = (const float*)d_in[12];
    const float* b2        = (const float*)d_in[13];
    const float* w3        = (const float*)d_in[14];
    const float* b3        = (const float*)d_in[15];
    const float* wc        = (const float*)d_in[16];
    const float* bc        = (const float*)d_in[17];
    float* out = (float*)d_out;

    const int smem1 = (11*34*34 + 4*8*11*9)  * 4;   //  63,536 B
    const int smem2 = (24*34*34 + 4*16*24*9) * 4;   // 166,272 B
    const int smem3 = (19*34*34 + 4*3*19*9)  * 4;   //  96,064 B
    cudaFuncSetAttribute(convlstm2<3,8,4>,
        cudaFuncAttributeMaxDynamicSharedMemorySize, smem1);
    cudaFuncSetAttribute(convlstm2<8,16,4>,
        cudaFuncAttributeMaxDynamicSharedMemorySize, smem2);
    cudaFuncSetAttribute(convlstm2<16,3,3>,
        cudaFuncAttributeMaxDynamicSharedMemorySize, smem3);

    // 1) mask -> fovea (r_t0), hr
    {
        int total = BATCH * HW;
        mask_kernel<<<(total + 255)/256, 256>>>(
            x, rand_mask, samples, out + OFF_FOVEA, out + OFF_HR);
    }

    dim3 grid(NN/32, NN/32, BATCH);   // (7, 7, 32)

    // 2) ConvLSTM 1: in = r_t0(3) + h1(8) -> h1n, c1n
    convlstm2<3,8,4><<<grid, 256, smem1>>>(
        out + OFF_FOVEA, h1, c1, w1, b1, out + OFF_H1, out + OFF_C1);

    // 3) ConvLSTM 2: in = h1n(8) + h2(16) -> h2n, c2n
    convlstm2<8,16,4><<<grid, 256, smem2>>>(
        out + OFF_H1, h2, c2, w2, b2, out + OFF_H2, out + OFF_C2);

    // 4) ConvLSTM 3: in = h2n(16) + h3(3) -> h3n, c3n
    convlstm2<16,3,3><<<grid, 256, smem3>>>(
        out + OFF_H2, h3, c3, w3, b3, out + OFF_H3, out + OFF_C3);

    // 5) reconstruction + hidden copy
    recon_kernel<<<grid, dim3(32,8)>>>(
        out + OFF_H3, wc, bc, out + OFF_RECON, out + OFF_HIDDEN);
}

// round 3
// speedup vs baseline: 1.5771x; 1.2737x over previous
#include <cuda_runtime.h>
#include <math.h>

#define NN 224
#define HW (NN*NN)
#define BATCH 32

typedef unsigned long long ull;

// d_out offsets (floats), in reference return order:
// h1n, c1n, h2n, c2n, h3n, c3n, reconstruction, fovea, hr, hidden
#define SZ8  ((size_t)BATCH*8*HW)
#define SZ16 ((size_t)BATCH*16*HW)
#define SZ3  ((size_t)BATCH*3*HW)
#define OFF_H1     ((size_t)0)
#define OFF_C1     (OFF_H1 + SZ8)
#define OFF_H2     (OFF_C1 + SZ8)
#define OFF_C2     (OFF_H2 + SZ16)
#define OFF_H3     (OFF_C2 + SZ16)
#define OFF_C3     (OFF_H3 + SZ3)
#define OFF_RECON  (OFF_C3 + SZ3)
#define OFF_FOVEA  (OFF_RECON + SZ3)
#define OFF_HR     (OFF_FOVEA + SZ3)
#define OFF_HIDDEN (OFF_HR + SZ3)

// fast activations: MUFU.EX2-based, rel err ~1e-6, well under 1e-3 budget
__device__ __forceinline__ float fast_sig(float x) {
    return __fdividef(1.0f, 1.0f + __expf(-x));
}
__device__ __forceinline__ float fast_tanh(float x) {
    // 1 - 2/(e^{2x}+1): e->0 => -1, e->inf => 1 (fdividef(2,inf)=0). Safe.
    float e = __expf(2.0f * x);
    return 1.0f - __fdividef(2.0f, e + 1.0f);
}

// ---- packed f32x2 helpers (sm_103a) --------------------------------------
__device__ __forceinline__ ull pack2(float lo, float hi) {
    ull r;
    asm("mov.b64 %0, {%1, %2};" : "=l"(r) : "f"(lo), "f"(hi));
    return r;
}
__device__ __forceinline__ void unpack2(ull v, float& lo, float& hi) {
    asm("mov.b64 {%0, %1}, %2;" : "=f"(lo), "=f"(hi) : "l"(v));
}
__device__ __forceinline__ ull fma2(ull a, ull b, ull c) {
    ull d;
    asm("fma.rn.f32x2 %0, %1, %2, %3;" : "=l"(d) : "l"(a), "l"(b), "l"(c));
    return d;
}

// ---------------------------------------------------------------------------
// Kernel 1: mask + fovea (= r_t0) + hr
// ---------------------------------------------------------------------------
__global__ void mask_kernel(const float* __restrict__ x,
                            const float* __restrict__ rand_mask,
                            const int*   __restrict__ samples,
                            float* __restrict__ fovea,
                            float* __restrict__ hr)
{
    int idx = blockIdx.x * blockDim.x + threadIdx.x;
    if (idx >= BATCH * HW) return;
    int b = idx / HW;
    int p = idx - b * HW;
    int y  = p / NN;
    int xx = p - y * NN;
    int s  = samples[b];
    int px = s / 7;
    int py = s - px * 7;
    bool patch = (y  >= px*32) && (y  < px*32 + 32) &&
                 (xx >= py*32) && (xx < py*32 + 32);
    bool m = (rand_mask[idx] > 0.95f) || patch;
    float fm = m     ? 1.0f : 0.0f;
    float fp = patch ? 1.0f : 0.0f;
#pragma unroll
    for (int c = 0; c < 3; c++) {
        float v = x[((size_t)b*3 + c)*HW + p];
        fovea[((size_t)b*3 + c)*HW + p] = v * fm;
        hr   [((size_t)b*3 + c)*HW + p] = v * fp;
    }
}

// ---------------------------------------------------------------------------
// Kernel 2: fused ConvLSTM step, f32x2 packed gate-pairs.
// 32x32 tile, 512 flat threads: thread (tx, tyy) handles col tx,
// 2 consecutive rows tyy*2, tyy*2+1.  (16 warps/block for latency hiding.)
// smem: CIN halo tiles (34x34) + weights reordered [ch][ci][tap][gate]
// so one LDS.64 yields a packed (w_i,w_f) / (w_o,w_g) pair.
// ---------------------------------------------------------------------------
template<int CX, int CH, int CHB>
__global__ void __launch_bounds__(512, 1)
convlstm2(const float* __restrict__ xin,
          const float* __restrict__ hin,
          const float* __restrict__ cin,
          const float* __restrict__ w,
          const float* __restrict__ bias,
          float* __restrict__ hout,
          float* __restrict__ cout)
{
    constexpr int CIN = CX + CH;
    constexpr int TSZ = 34 * 34;
    constexpr int WSZ = 4 * CH * CIN * 9;

    extern __shared__ float smem[];
    float* s_in = smem;                 // CIN * TSZ
    float* s_w  = smem + CIN * TSZ;     // WSZ, reordered

    const int tid = threadIdx.x;
    const int tx  = tid & 31;
    const int tyy = tid >> 5;           // 0..15
    const int x0  = blockIdx.x * 32;
    const int y0  = blockIdx.y * 32;
    const int b   = blockIdx.z;

    // input halo tiles
    for (int ci = 0; ci < CIN; ci++) {
        const float* src = (ci < CX)
            ? xin + ((size_t)b*CX + ci)      * HW
            : hin + ((size_t)b*CH + (ci-CX)) * HW;
        float* dst = s_in + ci * TSZ;
        for (int i = tid; i < TSZ; i += 512) {
            int yy = i / 34;
            int xx = i - yy * 34;
            int gy = y0 + yy - 1;
            int gx = x0 + xx - 1;
            float v = 0.0f;
            if (gy >= 0 && gy < NN && gx >= 0 && gx < NN)
                v = src[gy * NN + gx];
            dst[i] = v;
        }
    }
    // weights: global [gate*CH+ch][ci][tap] -> smem [ch][ci][tap][gate]
    for (int s = tid; s < WSZ; s += 512) {
        int g    = s & 3;
        int t    = (s >> 2) % 9;
        int rest = (s >> 2) / 9;        // ch*CIN + ci
        int ci   = rest % CIN;
        int ch   = rest / CIN;
        s_w[s] = w[((g*CH + ch)*CIN + ci)*9 + t];
    }
    __syncthreads();

    const int r0 = tyy * 2;             // top output row within tile

    for (int chb = 0; chb < CH; chb += CHB) {
        ull acc_if[CHB][2], acc_og[CHB][2];
#pragma unroll
        for (int c = 0; c < CHB; c++) {
            int ch = chb + c;
            ull bif = pack2(bias[ch],        bias[CH + ch]);
            ull bog = pack2(bias[2*CH + ch], bias[3*CH + ch]);
#pragma unroll
            for (int p = 0; p < 2; p++) { acc_if[c][p] = bif; acc_og[c][p] = bog; }
        }

        for (int ci = 0; ci < CIN; ci++) {
            const float* tile = s_in + ci * TSZ + r0 * 34 + tx;
            ull vd[4][3];
#pragma unroll
            for (int k = 0; k < 4; k++)
#pragma unroll
                for (int dx = 0; dx < 3; dx++) {
                    float v = tile[k*34 + dx];
                    vd[k][dx] = pack2(v, v);
                }
#pragma unroll
            for (int c = 0; c < CHB; c++) {
                const ull* wp = (const ull*)(s_w + ((chb + c)*CIN + ci) * 36);
#pragma unroll
                for (int dy = 0; dy < 3; dy++)
#pragma unroll
                    for (int dx = 0; dx < 3; dx++) {
                        ull wif = wp[(dy*3 + dx)*2];
                        ull wog = wp[(dy*3 + dx)*2 + 1];
#pragma unroll
                        for (int p = 0; p < 2; p++) {
                            acc_if[c][p] = fma2(vd[p + dy][dx], wif, acc_if[c][p]);
                            acc_og[c][p] = fma2(vd[p + dy][dx], wog, acc_og[c][p]);
                        }
                    }
            }
        }

        // epilogue: gating + activations
#pragma unroll
        for (int c = 0; c < CHB; c++) {
            int ch = chb + c;
#pragma unroll
            for (int p = 0; p < 2; p++) {
                float zi, zf, zo, zg;
                unpack2(acc_if[c][p], zi, zf);
                unpack2(acc_og[c][p], zo, zg);
                int y = y0 + r0 + p;
                size_t gidx = ((size_t)b*CH + ch)*HW + (size_t)y*NN + x0 + tx;
                float ig = fast_sig(zi);
                float fg = fast_sig(zf);
                float og = fast_sig(zo);
                float gg = fast_tanh(zg);
                float cp = cin[gidx];
                float cn = fg * cp + ig * gg;
                cout[gidx] = cn;
                hout[gidx] = og * fast_tanh(cn);
            }
        }
    }
}

// ---------------------------------------------------------------------------
// Kernel 3: reconstruction conv (3->3, 3x3) + hidden = h3n copy
// ---------------------------------------------------------------------------
__global__ void __launch_bounds__(256, 4)
recon_kernel(const float* __restrict__ h3,
             const float* __restrict__ wc,
             const float* __restrict__ bc,
             float* __restrict__ recon,
             float* __restrict__ hidden)
{
    __shared__ float s_in[3 * 34 * 34];
    __shared__ float s_w[3 * 3 * 9];
    __shared__ float s_b[3];

    const int tx  = threadIdx.x;
    const int ty  = threadIdx.y;
    const int tid = ty * 32 + tx;
    const int x0  = blockIdx.x * 32;
    const int y0  = blockIdx.y * 32;
    const int b   = blockIdx.z;

    for (int ci = 0; ci < 3; ci++) {
        const float* src = h3 + ((size_t)b*3 + ci) * HW;
        float* dst = s_in + ci * 1156;
        for (int i = tid; i < 1156; i += 256) {
            int yy = i / 34;
            int xx = i - yy * 34;
            int gy = y0 + yy - 1;
            int gx = x0 + xx - 1;
            float v = 0.0f;
            if (gy >= 0 && gy < NN && gx >= 0 && gx < NN)
                v = src[gy * NN + gx];
            dst[i] = v;
        }
    }
    if (tid < 81) s_w[tid] = wc[tid];
    if (tid < 3)  s_b[tid] = bc[tid];
    __syncthreads();

    for (int co = 0; co < 3; co++) {
        float acc[4];
#pragma unroll
        for (int p = 0; p < 4; p++) acc[p] = s_b[co];
        for (int ci = 0; ci < 3; ci++) {
            const float* tile = s_in + ci * 1156;
            const float* wp   = s_w + (co*3 + ci) * 9;
#pragma unroll
            for (int dy = 0; dy < 3; dy++)
#pragma unroll
                for (int dx = 0; dx < 3; dx++) {
                    float wv = wp[dy*3 + dx];
#pragma unroll
                    for (int p = 0; p < 4; p++) {
                        float v = tile[(ty + p*8 + dy)*34 + tx + dx];
                        acc[p] += v * wv;
                    }
                }
        }
#pragma unroll
        for (int p = 0; p < 4; p++) {
            int y = y0 + ty + p*8;
            size_t gidx = ((size_t)b*3 + co)*HW + (size_t)y*NN + x0 + tx;
            recon[gidx]  = acc[p];
            hidden[gidx] = s_in[co*1156 + (ty + p*8 + 1)*34 + tx + 1];
        }
    }
}

// ---------------------------------------------------------------------------
extern "C" void kernel_launch(void* const* d_in, const int* in_sizes, int n_in,
                              void* d_out, int out_size)
{
    const float* x         = (const float*)d_in[0];
    const float* h1        = (const float*)d_in[2];
    const float* c1        = (const float*)d_in[3];
    const float* h2        = (const float*)d_in[4];
    const float* c2        = (const float*)d_in[5];
    const float* h3        = (const float*)d_in[6];
    const float* c3        = (const float*)d_in[7];
    const float* rand_mask = (const float*)d_in[8];
    const int*   samples   = (const int*)  d_in[9];
    const float* w1        = (const float*)d_in[10];
    const float* b1        = (const float*)d_in[11];
    const float* w2        = (const float*)d_in[12];
    const float* b2        = (const float*)d_in[13];
    const float* w3        = (const float*)d_in[14];
    const float* b3        = (const float*)d_in[15];
    const float* wc        = (const float*)d_in[16];
    const float* bc        = (const float*)d_in[17];
    float* out = (float*)d_out;

    const int smem1 = (11*34*34 + 4*8*11*9)  * 4;   //  63,536 B
    const int smem2 = (24*34*34 + 4*16*24*9) * 4;   // 166,272 B
    const int smem3 = (19*34*34 + 4*3*19*9)  * 4;   //  96,064 B
    cudaFuncSetAttribute(convlstm2<3,8,4>,
        cudaFuncAttributeMaxDynamicSharedMemorySize, smem1);
    cudaFuncSetAttribute(convlstm2<8,16,4>,
        cudaFuncAttributeMaxDynamicSharedMemorySize, smem2);
    cudaFuncSetAttribute(convlstm2<16,3,3>,
        cudaFuncAttributeMaxDynamicSharedMemorySize, smem3);

    // 1) mask -> fovea (r_t0), hr
    {
        int total = BATCH * HW;
        mask_kernel<<<(total + 255)/256, 256>>>(
            x, rand_mask, samples, out + OFF_FOVEA, out + OFF_HR);
    }

    dim3 grid(NN/32, NN/32, BATCH);   // (7, 7, 32)

    // 2) ConvLSTM 1: in = r_t0(3) + h1(8) -> h1n, c1n
    convlstm2<3,8,4><<<grid, 512, smem1>>>(
        out + OFF_FOVEA, h1, c1, w1, b1, out + OFF_H1, out + OFF_C1);

    // 3) ConvLSTM 2: in = h1n(8) + h2(16) -> h2n, c2n
    convlstm2<8,16,4><<<grid, 512, smem2>>>(
        out + OFF_H1, h2, c2, w2, b2, out + OFF_H2, out + OFF_C2);

    // 4) ConvLSTM 3: in = h2n(16) + h3(3) -> h3n, c3n
    convlstm2<16,3,3><<<grid, 512, smem3>>>(
        out + OFF_H2, h3, c3, w3, b3, out + OFF_H3, out + OFF_C3);

    // 5) reconstruction + hidden copy
    recon_kernel<<<grid, dim3(32,8)>>>(
        out + OFF_H3, wc, bc, out + OFF_RECON, out + OFF_HIDDEN);
}

// round 4
// speedup vs baseline: 1.8415x; 1.1677x over previous
#include <cuda_runtime.h>
#include <math.h>

#define NN 224
#define HW (NN*NN)
#define BATCH 32

typedef unsigned long long ull;

// d_out offsets (floats), in reference return order:
// h1n, c1n, h2n, c2n, h3n, c3n, reconstruction, fovea, hr, hidden
#define SZ8  ((size_t)BATCH*8*HW)
#define SZ16 ((size_t)BATCH*16*HW)
#define SZ3  ((size_t)BATCH*3*HW)
#define OFF_H1     ((size_t)0)
#define OFF_C1     (OFF_H1 + SZ8)
#define OFF_H2     (OFF_C1 + SZ8)
#define OFF_C2     (OFF_H2 + SZ16)
#define OFF_H3     (OFF_C2 + SZ16)
#define OFF_C3     (OFF_H3 + SZ3)
#define OFF_RECON  (OFF_C3 + SZ3)
#define OFF_FOVEA  (OFF_RECON + SZ3)
#define OFF_HR     (OFF_FOVEA + SZ3)
#define OFF_HIDDEN (OFF_HR + SZ3)

// fast activations: MUFU.EX2-based, rel err ~1e-6, well under 1e-3 budget
__device__ __forceinline__ float fast_sig(float x) {
    return __fdividef(1.0f, 1.0f + __expf(-x));
}
__device__ __forceinline__ float fast_tanh(float x) {
    float e = __expf(2.0f * x);
    return 1.0f - __fdividef(2.0f, e + 1.0f);
}

// ---- packed f32x2 helpers (sm_103a) --------------------------------------
__device__ __forceinline__ ull pack2(float lo, float hi) {
    ull r;
    asm("mov.b64 %0, {%1, %2};" : "=l"(r) : "f"(lo), "f"(hi));
    return r;
}
__device__ __forceinline__ void unpack2(ull v, float& lo, float& hi) {
    asm("mov.b64 {%0, %1}, %2;" : "=f"(lo), "=f"(hi) : "l"(v));
}
__device__ __forceinline__ ull fma2(ull a, ull b, ull c) {
    ull d;
    asm("fma.rn.f32x2 %0, %1, %2, %3;" : "=l"(d) : "l"(a), "l"(b), "l"(c));
    return d;
}

// ---------------------------------------------------------------------------
// Kernel 1: mask + fovea (= r_t0) + hr
// ---------------------------------------------------------------------------
__global__ void mask_kernel(const float* __restrict__ x,
                            const float* __restrict__ rand_mask,
                            const int*   __restrict__ samples,
                            float* __restrict__ fovea,
                            float* __restrict__ hr)
{
    int idx = blockIdx.x * blockDim.x + threadIdx.x;
    if (idx >= BATCH * HW) return;
    int b = idx / HW;
    int p = idx - b * HW;
    int y  = p / NN;
    int xx = p - y * NN;
    int s  = samples[b];
    int px = s / 7;
    int py = s - px * 7;
    bool patch = (y  >= px*32) && (y  < px*32 + 32) &&
                 (xx >= py*32) && (xx < py*32 + 32);
    bool m = (rand_mask[idx] > 0.95f) || patch;
    float fm = m     ? 1.0f : 0.0f;
    float fp = patch ? 1.0f : 0.0f;
#pragma unroll
    for (int c = 0; c < 3; c++) {
        float v = x[((size_t)b*3 + c)*HW + p];
        fovea[((size_t)b*3 + c)*HW + p] = v * fm;
        hr   [((size_t)b*3 + c)*HW + p] = v * fp;
    }
}

// ---------------------------------------------------------------------------
// Kernel 2: fused ConvLSTM step, f32x2 packed gate-pairs.
// TW x 32 output tile, TW*16 threads: thread (tx, tyy) handles col tx,
// 2 consecutive rows tyy*2, tyy*2+1.
// smem: CIN halo tiles ((32+2) x (TW+2)) + weights reordered
// [ch][ci][tap][gate] so one LDS.64 yields packed (w_i,w_f) / (w_o,w_g).
// MINB forces register cap for multi-block residency.
// ---------------------------------------------------------------------------
template<int CX, int CH, int CHB, int TW, int MINB>
__global__ void __launch_bounds__(TW*16, MINB)
convlstm2(const float* __restrict__ xin,
          const float* __restrict__ hin,
          const float* __restrict__ cin,
          const float* __restrict__ w,
          const float* __restrict__ bias,
          float* __restrict__ hout,
          float* __restrict__ cout)
{
    constexpr int CIN    = CX + CH;
    constexpr int HALO_W = TW + 2;
    constexpr int TSZ    = 34 * HALO_W;
    constexpr int WSZ    = 4 * CH * CIN * 9;
    constexpr int NT     = TW * 16;

    extern __shared__ float smem[];
    float* s_in = smem;                 // CIN * TSZ
    float* s_w  = smem + CIN * TSZ;     // WSZ, reordered

    const int tid = threadIdx.x;
    const int tx  = tid % TW;
    const int tyy = tid / TW;           // 0..15
    const int x0  = blockIdx.x * TW;
    const int y0  = blockIdx.y * 32;
    const int b   = blockIdx.z;

    // input halo tiles
    for (int ci = 0; ci < CIN; ci++) {
        const float* src = (ci < CX)
            ? xin + ((size_t)b*CX + ci)      * HW
            : hin + ((size_t)b*CH + (ci-CX)) * HW;
        float* dst = s_in + ci * TSZ;
        for (int i = tid; i < TSZ; i += NT) {
            int yy = i / HALO_W;
            int xx = i - yy * HALO_W;
            int gy = y0 + yy - 1;
            int gx = x0 + xx - 1;
            float v = 0.0f;
            if (gy >= 0 && gy < NN && gx >= 0 && gx < NN)
                v = src[gy * NN + gx];
            dst[i] = v;
        }
    }
    // weights: global [gate*CH+ch][ci][tap] -> smem [ch][ci][tap][gate]
    for (int s = tid; s < WSZ; s += NT) {
        int g    = s & 3;
        int t    = (s >> 2) % 9;
        int rest = (s >> 2) / 9;        // ch*CIN + ci
        int ci   = rest % CIN;
        int ch   = rest / CIN;
        s_w[s] = w[((g*CH + ch)*CIN + ci)*9 + t];
    }
    __syncthreads();

    const int r0 = tyy * 2;             // top output row within tile
    const int gx = x0 + tx;
    const bool valid = (gx < NN);

    for (int chb = 0; chb < CH; chb += CHB) {
        ull acc_if[CHB][2], acc_og[CHB][2];
#pragma unroll
        for (int c = 0; c < CHB; c++) {
            int ch = chb + c;
            ull bif = pack2(bias[ch],        bias[CH + ch]);
            ull bog = pack2(bias[2*CH + ch], bias[3*CH + ch]);
#pragma unroll
            for (int p = 0; p < 2; p++) { acc_if[c][p] = bif; acc_og[c][p] = bog; }
        }

        for (int ci = 0; ci < CIN; ci++) {
            const float* tile = s_in + ci * TSZ + r0 * HALO_W + tx;
            ull vd[4][3];
#pragma unroll
            for (int k = 0; k < 4; k++)
#pragma unroll
                for (int dx = 0; dx < 3; dx++) {
                    float v = tile[k*HALO_W + dx];
                    vd[k][dx] = pack2(v, v);
                }
#pragma unroll
            for (int c = 0; c < CHB; c++) {
                const ull* wp = (const ull*)(s_w + ((chb + c)*CIN + ci) * 36);
#pragma unroll
                for (int dy = 0; dy < 3; dy++)
#pragma unroll
                    for (int dx = 0; dx < 3; dx++) {
                        ull wif = wp[(dy*3 + dx)*2];
                        ull wog = wp[(dy*3 + dx)*2 + 1];
#pragma unroll
                        for (int p = 0; p < 2; p++) {
                            acc_if[c][p] = fma2(vd[p + dy][dx], wif, acc_if[c][p]);
                            acc_og[c][p] = fma2(vd[p + dy][dx], wog, acc_og[c][p]);
                        }
                    }
            }
        }

        // epilogue: gating + activations
        if (valid) {
#pragma unroll
            for (int c = 0; c < CHB; c++) {
                int ch = chb + c;
#pragma unroll
                for (int p = 0; p < 2; p++) {
                    float zi, zf, zo, zg;
                    unpack2(acc_if[c][p], zi, zf);
                    unpack2(acc_og[c][p], zo, zg);
                    int y = y0 + r0 + p;
                    size_t gidx = ((size_t)b*CH + ch)*HW + (size_t)y*NN + gx;
                    float ig = fast_sig(zi);
                    float fg = fast_sig(zf);
                    float og = fast_sig(zo);
                    float gg = fast_tanh(zg);
                    float cp = cin[gidx];
                    float cn = fg * cp + ig * gg;
                    cout[gidx] = cn;
                    hout[gidx] = og * fast_tanh(cn);
                }
            }
        }
    }
}

// ---------------------------------------------------------------------------
// Kernel 3: reconstruction conv (3->3, 3x3) + hidden = h3n copy
// ---------------------------------------------------------------------------
__global__ void __launch_bounds__(256, 4)
recon_kernel(const float* __restrict__ h3,
             const float* __restrict__ wc,
             const float* __restrict__ bc,
             float* __restrict__ recon,
             float* __restrict__ hidden)
{
    __shared__ float s_in[3 * 34 * 34];
    __shared__ float s_w[3 * 3 * 9];
    __shared__ float s_b[3];

    const int tx  = threadIdx.x;
    const int ty  = threadIdx.y;
    const int tid = ty * 32 + tx;
    const int x0  = blockIdx.x * 32;
    const int y0  = blockIdx.y * 32;
    const int b   = blockIdx.z;

    for (int ci = 0; ci < 3; ci++) {
        const float* src = h3 + ((size_t)b*3 + ci) * HW;
        float* dst = s_in + ci * 1156;
        for (int i = tid; i < 1156; i += 256) {
            int yy = i / 34;
            int xx = i - yy * 34;
            int gy = y0 + yy - 1;
            int gx = x0 + xx - 1;
            float v = 0.0f;
            if (gy >= 0 && gy < NN && gx >= 0 && gx < NN)
                v = src[gy * NN + gx];
            dst[i] = v;
        }
    }
    if (tid < 81) s_w[tid] = wc[tid];
    if (tid < 3)  s_b[tid] = bc[tid];
    __syncthreads();

    for (int co = 0; co < 3; co++) {
        float acc[4];
#pragma unroll
        for (int p = 0; p < 4; p++) acc[p] = s_b[co];
        for (int ci = 0; ci < 3; ci++) {
            const float* tile = s_in + ci * 1156;
            const float* wp   = s_w + (co*3 + ci) * 9;
#pragma unroll
            for (int dy = 0; dy < 3; dy++)
#pragma unroll
                for (int dx = 0; dx < 3; dx++) {
                    float wv = wp[dy*3 + dx];
#pragma unroll
                    for (int p = 0; p < 4; p++) {
                        float v = tile[(ty + p*8 + dy)*34 + tx + dx];
                        acc[p] += v * wv;
                    }
                }
        }
#pragma unroll
        for (int p = 0; p < 4; p++) {
            int y = y0 + ty + p*8;
            size_t gidx = ((size_t)b*3 + co)*HW + (size_t)y*NN + x0 + tx;
            recon[gidx]  = acc[p];
            hidden[gidx] = s_in[co*1156 + (ty + p*8 + 1)*34 + tx + 1];
        }
    }
}

// ---------------------------------------------------------------------------
extern "C" void kernel_launch(void* const* d_in, const int* in_sizes, int n_in,
                              void* d_out, int out_size)
{
    const float* x         = (const float*)d_in[0];
    const float* h1        = (const float*)d_in[2];
    const float* c1        = (const float*)d_in[3];
    const float* h2        = (const float*)d_in[4];
    const float* c2        = (const float*)d_in[5];
    const float* h3        = (const float*)d_in[6];
    const float* c3        = (const float*)d_in[7];
    const float* rand_mask = (const float*)d_in[8];
    const int*   samples   = (const int*)  d_in[9];
    const float* w1        = (const float*)d_in[10];
    const float* b1        = (const float*)d_in[11];
    const float* w2        = (const float*)d_in[12];
    const float* b2        = (const float*)d_in[13];
    const float* w3        = (const float*)d_in[14];
    const float* b3        = (const float*)d_in[15];
    const float* wc        = (const float*)d_in[16];
    const float* bc        = (const float*)d_in[17];
    float* out = (float*)d_out;

    // conv1: TW=32, 512 thr, 2 blocks/SM target
    const int smem1 = (11*34*34 + 4*8*11*9) * 4;            //  63,536 B
    // conv2: TW=48, 768 thr, halo 34x50
    const int smem2 = (24*34*50 + 4*16*24*9) * 4;           // 218,496 B
    // conv3: TW=32, 512 thr, 2 blocks/SM target
    const int smem3 = (19*34*34 + 4*3*19*9) * 4;            //  96,064 B

    cudaFuncSetAttribute((const void*)convlstm2<3,8,2,32,2>,
        cudaFuncAttributeMaxDynamicSharedMemorySize, smem1);
    cudaFuncSetAttribute((const void*)convlstm2<8,16,4,48,1>,
        cudaFuncAttributeMaxDynamicSharedMemorySize, smem2);
    cudaFuncSetAttribute((const void*)convlstm2<16,3,3,32,2>,
        cudaFuncAttributeMaxDynamicSharedMemorySize, smem3);

    // 1) mask -> fovea (r_t0), hr
    {
        int total = BATCH * HW;
        mask_kernel<<<(total + 255)/256, 256>>>(
            x, rand_mask, samples, out + OFF_FOVEA, out + OFF_HR);
    }

    dim3 grid32(7, 7, BATCH);            // 32-wide tiles
    dim3 grid48(5, 7, BATCH);            // 48-wide tiles (240 covers 224)

    // 2) ConvLSTM 1: in = r_t0(3) + h1(8) -> h1n, c1n
    convlstm2<3,8,2,32,2><<<grid32, 512, smem1>>>(
        out + OFF_FOVEA, h1, c1, w1, b1, out + OFF_H1, out + OFF_C1);

    // 3) ConvLSTM 2: in = h1n(8) + h2(16) -> h2n, c2n
    convlstm2<8,16,4,48,1><<<grid48, 768, smem2>>>(
        out + OFF_H1, h2, c2, w2, b2, out + OFF_H2, out + OFF_C2);

    // 4) ConvLSTM 3: in = h2n(16) + h3(3) -> h3n, c3n
    convlstm2<16,3,3,32,2><<<grid32, 512, smem3>>>(
        out + OFF_H2, h3, c3, w3, b3, out + OFF_H3, out + OFF_C3);

    // 5) reconstruction + hidden copy
    recon_kernel<<<grid32, dim3(32,8)>>>(
        out + OFF_H3, wc, bc, out + OFF_RECON, out + OFF_HIDDEN);
}

// round 6
// speedup vs baseline: 2.2394x; 1.2161x over previous
#include <cuda_runtime.h>
#include <math.h>

#define NN 224
#define HW (NN*NN)
#define BATCH 32

typedef unsigned long long ull;

// d_out offsets (floats), in reference return order:
// h1n, c1n, h2n, c2n, h3n, c3n, reconstruction, fovea, hr, hidden
#define SZ8  ((size_t)BATCH*8*HW)
#define SZ16 ((size_t)BATCH*16*HW)
#define SZ3  ((size_t)BATCH*3*HW)
#define OFF_H1     ((size_t)0)
#define OFF_C1     (OFF_H1 + SZ8)
#define OFF_H2     (OFF_C1 + SZ8)
#define OFF_C2     (OFF_H2 + SZ16)
#define OFF_H3     (OFF_C2 + SZ16)
#define OFF_C3     (OFF_H3 + SZ3)
#define OFF_RECON  (OFF_C3 + SZ3)
#define OFF_FOVEA  (OFF_RECON + SZ3)
#define OFF_HR     (OFF_FOVEA + SZ3)
#define OFF_HIDDEN (OFF_HR + SZ3)

// fast activations: MUFU.EX2-based, rel err ~1e-6, well under 1e-3 budget
__device__ __forceinline__ float fast_sig(float x) {
    return __fdividef(1.0f, 1.0f + __expf(-x));
}
__device__ __forceinline__ float fast_tanh(float x) {
    float e = __expf(2.0f * x);
    return 1.0f - __fdividef(2.0f, e + 1.0f);
}

// ---- packed f32x2 helpers (sm_103a) --------------------------------------
__device__ __forceinline__ ull pack2(float lo, float hi) {
    ull r;
    asm("mov.b64 %0, {%1, %2};" : "=l"(r) : "f"(lo), "f"(hi));
    return r;
}
__device__ __forceinline__ void unpack2(ull v, float& lo, float& hi) {
    asm("mov.b64 {%0, %1}, %2;" : "=f"(lo), "=f"(hi) : "l"(v));
}
__device__ __forceinline__ ull fma2(ull a, ull b, ull c) {
    ull d;
    asm("fma.rn.f32x2 %0, %1, %2, %3;" : "=l"(d) : "l"(a), "l"(b), "l"(c));
    return d;
}

// ---------------------------------------------------------------------------
// Fused ConvLSTM step, f32x2 packed gate-pairs.
// TW x TH output tile, TW*TH/2 threads; thread handles col tx,
// 2 consecutive rows.
// smem: CIN halo tiles ((TH+2) x (TW+2)) + weights reordered
// [ch][ci][tap][gate] so one LDS.64 yields packed (w_i,w_f)/(w_o,w_g).
// STAGE_W: stage only CHB channels of weights per outer iteration (conv2).
// FUSE_MASK: layer-1 computes r_t0 = x*mask inline and emits fovea/hr.
// ---------------------------------------------------------------------------
template<int CX, int CH, int CHB, int TW, int TH, int MINB,
         bool FUSE_MASK, bool STAGE_W>
__global__ void __launch_bounds__(TW*TH/2, MINB)
convlstm2(const float* __restrict__ xin,
          const float* __restrict__ hin,
          const float* __restrict__ cin,
          const float* __restrict__ w,
          const float* __restrict__ bias,
          float* __restrict__ hout,
          float* __restrict__ cout,
          const float* __restrict__ rand_mask,
          const int*   __restrict__ samples,
          float* __restrict__ fovea,
          float* __restrict__ hr)
{
    constexpr int CIN    = CX + CH;
    constexpr int HALO_W = TW + 2;
    constexpr int HALO_H = TH + 2;
    constexpr int TSZ    = HALO_H * HALO_W;
    constexpr int NT     = TW * TH / 2;
    constexpr int WSTG   = STAGE_W ? (4 * CHB * CIN * 9) : (4 * CH * CIN * 9);

    extern __shared__ float smem[];
    float* s_in = smem;                 // CIN * TSZ
    float* s_w  = smem + CIN * TSZ;     // WSTG, reordered

    const int tid = threadIdx.x;
    const int tx  = tid % TW;
    const int tyy = tid / TW;           // 0..TH/2-1
    const int x0  = blockIdx.x * TW;
    const int y0  = blockIdx.y * TH;
    const int b   = blockIdx.z;

    int px32 = 0, py32 = 0;
    if (FUSE_MASK) {
        int s = samples[b];
        px32 = (s / 7) * 32;
        py32 = (s - (s / 7) * 7) * 32;
    }

    // ---- input halo tiles ----
    for (int ci = 0; ci < CIN; ci++) {
        const float* src = (ci < CX)
            ? xin + ((size_t)b*CX + ci)      * HW
            : hin + ((size_t)b*CH + (ci-CX)) * HW;
        float* dst = s_in + ci * TSZ;
        for (int i = tid; i < TSZ; i += NT) {
            int yy = i / HALO_W;
            int xx = i - yy * HALO_W;
            int gy = y0 + yy - 1;
            int gx = x0 + xx - 1;
            float v = 0.0f;
            if (gy >= 0 && gy < NN && gx >= 0 && gx < NN) {
                float xv = src[gy * NN + gx];
                if (FUSE_MASK && ci < CX) {
                    bool patch = (gy >= px32) && (gy < px32 + 32) &&
                                 (gx >= py32) && (gx < py32 + 32);
                    float rm = rand_mask[(size_t)b*HW + gy*NN + gx];
                    bool m = (rm > 0.95f) || patch;
                    float vm = m ? xv : 0.0f;
                    v = vm;
                    // interior pixels: also emit fovea / hr
                    if (yy >= 1 && yy <= TH && xx >= 1 && xx <= TW) {
                        size_t o = ((size_t)b*CX + ci)*HW + (size_t)gy*NN + gx;
                        fovea[o] = vm;
                        hr[o]    = patch ? xv : 0.0f;
                    }
                } else {
                    v = xv;
                }
            }
            dst[i] = v;
        }
    }
    // ---- resident weights (non-staged) ----
    if (!STAGE_W) {
        for (int s = tid; s < 4*CH*CIN*9; s += NT) {
            int g    = s & 3;
            int t    = (s >> 2) % 9;
            int rest = (s >> 2) / 9;    // ch*CIN + ci
            int ci   = rest % CIN;
            int ch   = rest / CIN;
            s_w[s] = w[((g*CH + ch)*CIN + ci)*9 + t];
        }
    }
    __syncthreads();

    const int r0 = tyy * 2;

    for (int chb = 0; chb < CH; chb += CHB) {
        if (STAGE_W) {
            __syncthreads();            // protect previous iteration's reads
            for (int s = tid; s < WSTG; s += NT) {
                int g    = s & 3;
                int t    = (s >> 2) % 9;
                int rest = (s >> 2) / 9;  // c*CIN + ci
                int ci   = rest % CIN;
                int c    = rest / CIN;    // 0..CHB-1
                s_w[s] = w[((g*CH + chb + c)*CIN + ci)*9 + t];
            }
            __syncthreads();
        }

        ull acc_if[CHB][2], acc_og[CHB][2];
#pragma unroll
        for (int c = 0; c < CHB; c++) {
            int ch = chb + c;
            ull bif = pack2(bias[ch],        bias[CH + ch]);
            ull bog = pack2(bias[2*CH + ch], bias[3*CH + ch]);
#pragma unroll
            for (int p = 0; p < 2; p++) { acc_if[c][p] = bif; acc_og[c][p] = bog; }
        }

        for (int ci = 0; ci < CIN; ci++) {
            const float* tile = s_in + ci * TSZ + r0 * HALO_W + tx;
            ull vd[4][3];
#pragma unroll
            for (int k = 0; k < 4; k++)
#pragma unroll
                for (int dx = 0; dx < 3; dx++) {
                    float v = tile[k*HALO_W + dx];
                    vd[k][dx] = pack2(v, v);
                }
#pragma unroll
            for (int c = 0; c < CHB; c++) {
                const ull* wp = STAGE_W
                    ? (const ull*)(s_w + (c*CIN + ci) * 36)
                    : (const ull*)(s_w + ((chb + c)*CIN + ci) * 36);
#pragma unroll
                for (int dy = 0; dy < 3; dy++)
#pragma unroll
                    for (int dx = 0; dx < 3; dx++) {
                        ull wif = wp[(dy*3 + dx)*2];
                        ull wog = wp[(dy*3 + dx)*2 + 1];
#pragma unroll
                        for (int p = 0; p < 2; p++) {
                            acc_if[c][p] = fma2(vd[p + dy][dx], wif, acc_if[c][p]);
                            acc_og[c][p] = fma2(vd[p + dy][dx], wog, acc_og[c][p]);
                        }
                    }
            }
        }

        // epilogue: gating + activations
#pragma unroll
        for (int c = 0; c < CHB; c++) {
            int ch = chb + c;
#pragma unroll
            for (int p = 0; p < 2; p++) {
                float zi, zf, zo, zg;
                unpack2(acc_if[c][p], zi, zf);
                unpack2(acc_og[c][p], zo, zg);
                int y = y0 + r0 + p;
                size_t gidx = ((size_t)b*CH + ch)*HW + (size_t)y*NN + x0 + tx;
                float ig = fast_sig(zi);
                float fg = fast_sig(zf);
                float og = fast_sig(zo);
                float gg = fast_tanh(zg);
                float cp = cin[gidx];
                float cn = fg * cp + ig * gg;
                cout[gidx] = cn;
                hout[gidx] = og * fast_tanh(cn);
            }
        }
    }
}

// ---------------------------------------------------------------------------
// Reconstruction conv (3->3, 3x3) + hidden = h3n copy
// ---------------------------------------------------------------------------
__global__ void __launch_bounds__(256, 4)
recon_kernel(const float* __restrict__ h3,
             const float* __restrict__ wc,
             const float* __restrict__ bc,
             float* __restrict__ recon,
             float* __restrict__ hidden)
{
    __shared__ float s_in[3 * 34 * 34];
    __shared__ float s_w[3 * 3 * 9];
    __shared__ float s_b[3];

    const int tx  = threadIdx.x;
    const int ty  = threadIdx.y;
    const int tid = ty * 32 + tx;
    const int x0  = blockIdx.x * 32;
    const int y0  = blockIdx.y * 32;
    const int b   = blockIdx.z;

    for (int ci = 0; ci < 3; ci++) {
        const float* src = h3 + ((size_t)b*3 + ci) * HW;
        float* dst = s_in + ci * 1156;
        for (int i = tid; i < 1156; i += 256) {
            int yy = i / 34;
            int xx = i - yy * 34;
            int gy = y0 + yy - 1;
            int gx = x0 + xx - 1;
            float v = 0.0f;
            if (gy >= 0 && gy < NN && gx >= 0 && gx < NN)
                v = src[gy * NN + gx];
            dst[i] = v;
        }
    }
    if (tid < 81) s_w[tid] = wc[tid];
    if (tid < 3)  s_b[tid] = bc[tid];
    __syncthreads();

    for (int co = 0; co < 3; co++) {
        float acc[4];
#pragma unroll
        for (int p = 0; p < 4; p++) acc[p] = s_b[co];
        for (int ci = 0; ci < 3; ci++) {
            const float* tile = s_in + ci * 1156;
            const float* wp   = s_w + (co*3 + ci) * 9;
#pragma unroll
            for (int dy = 0; dy < 3; dy++)
#pragma unroll
                for (int dx = 0; dx < 3; dx++) {
                    float wv = wp[dy*3 + dx];
#pragma unroll
                    for (int p = 0; p < 4; p++) {
                        float v = tile[(ty + p*8 + dy)*34 + tx + dx];
                        acc[p] += v * wv;
                    }
                }
        }
#pragma unroll
        for (int p = 0; p < 4; p++) {
            int y = y0 + ty + p*8;
            size_t gidx = ((size_t)b*3 + co)*HW + (size_t)y*NN + x0 + tx;
            recon[gidx]  = acc[p];
            hidden[gidx] = s_in[co*1156 + (ty + p*8 + 1)*34 + tx + 1];
        }
    }
}

// ---------------------------------------------------------------------------
extern "C" void kernel_launch(void* const* d_in, const int* in_sizes, int n_in,
                              void* d_out, int out_size)
{
    const float* x         = (const float*)d_in[0];
    const float* h1        = (const float*)d_in[2];
    const float* c1        = (const float*)d_in[3];
    const float* h2        = (const float*)d_in[4];
    const float* c2        = (const float*)d_in[5];
    const float* h3        = (const float*)d_in[6];
    const float* c3        = (const float*)d_in[7];
    const float* rand_mask = (const float*)d_in[8];
    const int*   samples   = (const int*)  d_in[9];
    const float* w1        = (const float*)d_in[10];
    const float* b1        = (const float*)d_in[11];
    const float* w2        = (const float*)d_in[12];
    const float* b2        = (const float*)d_in[13];
    const float* w3        = (const float*)d_in[14];
    const float* b3        = (const float*)d_in[15];
    const float* wc        = (const float*)d_in[16];
    const float* bc        = (const float*)d_in[17];
    float* out = (float*)d_out;

    // conv1: fused mask, full weights. smem = 11*18*34 + 4*8*11*9 floats
    const int smem1 = (11*18*34 + 4*8*11*9) * 4;   // 39,600 B  -> 4 blocks/SM
    // conv2: staged weights (CHB=4). smem = 24*18*34 + 4*4*24*9 floats
    const int smem2 = (24*18*34 + 4*4*24*9) * 4;   // 72,576 B  -> 3 blocks/SM
    // conv3: full weights. smem = 19*18*34 + 4*3*19*9 floats
    const int smem3 = (19*18*34 + 4*3*19*9) * 4;   // 54,720 B  -> 4 blocks/SM

    auto k1 = convlstm2<3, 8, 4, 32, 16, 4, true,  false>;
    auto k2 = convlstm2<8, 16, 4, 32, 16, 3, false, true >;
    auto k3 = convlstm2<16, 3, 3, 32, 16, 4, false, false>;

    cudaFuncSetAttribute((const void*)k1,
        cudaFuncAttributeMaxDynamicSharedMemorySize, smem1);
    cudaFuncSetAttribute((const void*)k2,
        cudaFuncAttributeMaxDynamicSharedMemorySize, smem2);
    cudaFuncSetAttribute((const void*)k3,
        cudaFuncAttributeMaxDynamicSharedMemorySize, smem3);

    dim3 grid(NN/32, NN/16, BATCH);    // (7, 14, 32)

    // 1) ConvLSTM 1 (fused mask): in = r_t0(3) + h1(8) -> h1n, c1n, fovea, hr
    k1<<<grid, 256, smem1>>>(
        x, h1, c1, w1, b1, out + OFF_H1, out + OFF_C1,
        rand_mask, samples, out + OFF_FOVEA, out + OFF_HR);

    // 2) ConvLSTM 2: in = h1n(8) + h2(16) -> h2n, c2n
    k2<<<grid, 256, smem2>>>(
        out + OFF_H1, h2, c2, w2, b2, out + OFF_H2, out + OFF_C2,
        nullptr, nullptr, nullptr, nullptr);

    // 3) ConvLSTM 3: in = h2n(16) + h3(3) -> h3n, c3n
    k3<<<grid, 256, smem3>>>(
        out + OFF_H2, h3, c3, w3, b3, out + OFF_H3, out + OFF_C3,
        nullptr, nullptr, nullptr, nullptr);

    // 4) reconstruction + hidden copy
    recon_kernel<<<dim3(7,7,BATCH), dim3(32,8)>>>(
        out + OFF_H3, wc, bc, out + OFF_RECON, out + OFF_HIDDEN);
}